// round 2
// baseline (speedup 1.0000x reference)
#include <cuda_runtime.h>

#define BB 8
#define TT 2048
#define DD 1024
#define MT (BB * TT)   // 16384 rows

// Scratch for projections (allocation-free rule: __device__ globals)
__device__ float g_q[(size_t)MT * DD];
__device__ float g_k[(size_t)MT * DD];
__device__ float g_v[(size_t)MT * DD];

// ---------------------------------------------------------------------------
// C[M,N] = X[M,K] @ W[N,K]^T + bias   (both operands K-contiguous)
// 128x128 block, BK=8, 256 threads, 8x8 microtile (4+4 split layout)
// ---------------------------------------------------------------------------
__global__ __launch_bounds__(256) void sgemm_bias_kernel(
    const float* __restrict__ X, const float* __restrict__ W,
    const float* __restrict__ bias, float* __restrict__ C) {
    const int K = DD, N = DD;
    __shared__ float As[8][128];
    __shared__ float Bs[8][128];

    const int tid  = threadIdx.x;
    const int bm   = blockIdx.y * 128;
    const int bn   = blockIdx.x * 128;
    const int lrow = tid >> 1;          // 0..127
    const int lcol = (tid & 1) * 4;     // 0 or 4

    const float* Xg = X + (size_t)(bm + lrow) * K + lcol;
    const float* Wg = W + (size_t)(bn + lrow) * K + lcol;

    const int tx = tid & 15;            // 0..15 -> N
    const int ty = tid >> 4;            // 0..15 -> M

    float acc[8][8];
#pragma unroll
    for (int i = 0; i < 8; i++)
#pragma unroll
        for (int j = 0; j < 8; j++) acc[i][j] = 0.f;

    for (int k0 = 0; k0 < K; k0 += 8) {
        float4 a  = *(const float4*)(Xg + k0);
        float4 b4 = *(const float4*)(Wg + k0);
        As[lcol + 0][lrow] = a.x;
        As[lcol + 1][lrow] = a.y;
        As[lcol + 2][lrow] = a.z;
        As[lcol + 3][lrow] = a.w;
        Bs[lcol + 0][lrow] = b4.x;
        Bs[lcol + 1][lrow] = b4.y;
        Bs[lcol + 2][lrow] = b4.z;
        Bs[lcol + 3][lrow] = b4.w;
        __syncthreads();

#pragma unroll
        for (int kk = 0; kk < 8; kk++) {
            float ra[8], rb[8];
            *(float4*)&ra[0] = *(const float4*)&As[kk][ty * 4];
            *(float4*)&ra[4] = *(const float4*)&As[kk][64 + ty * 4];
            *(float4*)&rb[0] = *(const float4*)&Bs[kk][tx * 4];
            *(float4*)&rb[4] = *(const float4*)&Bs[kk][64 + tx * 4];
#pragma unroll
            for (int i = 0; i < 8; i++)
#pragma unroll
                for (int j = 0; j < 8; j++)
                    acc[i][j] = fmaf(ra[i], rb[j], acc[i][j]);
        }
        __syncthreads();
    }

    // Epilogue: vectorized stores, bias fused. Columns bn+tx*4.. and bn+64+tx*4..
    const float4 bias_lo = *(const float4*)&bias[bn + tx * 4];
    const float4 bias_hi = *(const float4*)&bias[bn + 64 + tx * 4];
#pragma unroll
    for (int i = 0; i < 8; i++) {
        int row = bm + ((i < 4) ? (ty * 4 + i) : (64 + ty * 4 + (i - 4)));
        float4 lo, hi;
        lo.x = acc[i][0] + bias_lo.x;
        lo.y = acc[i][1] + bias_lo.y;
        lo.z = acc[i][2] + bias_lo.z;
        lo.w = acc[i][3] + bias_lo.w;
        hi.x = acc[i][4] + bias_hi.x;
        hi.y = acc[i][5] + bias_hi.y;
        hi.z = acc[i][6] + bias_hi.z;
        hi.w = acc[i][7] + bias_hi.w;
        *(float4*)&C[(size_t)row * N + bn + tx * 4]      = lo;
        *(float4*)&C[(size_t)row * N + bn + 64 + tx * 4] = hi;
    }
}

// ---------------------------------------------------------------------------
// Per-channel decay scan: mem_t = decay[d]*mem_{t-1} + k_t*v_t ; out = q_t*mem_t
// One thread per (b, d). Loads coalesced along d.
// ---------------------------------------------------------------------------
__global__ __launch_bounds__(64) void retention_scan_kernel(
    const float* __restrict__ decay, float* __restrict__ out) {
    int idx = blockIdx.x * blockDim.x + threadIdx.x;
    if (idx >= BB * DD) return;
    int b = idx >> 10;          // / DD
    int d = idx & (DD - 1);

    const float dec = decay[d];
    size_t base = (size_t)b * TT * DD + d;

    float mem = 0.f;
#pragma unroll 4
    for (int t = 0; t < TT; t++) {
        size_t off = base + (size_t)t * DD;
        float kv = g_k[off] * g_v[off];
        mem = fmaf(dec, mem, kv);
        out[off] = g_q[off] * mem;
    }
}

extern "C" void kernel_launch(void* const* d_in, const int* in_sizes, int n_in,
                              void* d_out, int out_size) {
    const float* x     = (const float*)d_in[0];
    const float* Wq    = (const float*)d_in[1];
    const float* bq    = (const float*)d_in[2];
    const float* Wk    = (const float*)d_in[3];
    const float* bk    = (const float*)d_in[4];
    const float* Wv    = (const float*)d_in[5];
    const float* bv    = (const float*)d_in[6];
    const float* decay = (const float*)d_in[7];
    float* out = (float*)d_out;

    float *q_ptr, *k_ptr, *v_ptr;
    cudaGetSymbolAddress((void**)&q_ptr, g_q);
    cudaGetSymbolAddress((void**)&k_ptr, g_k);
    cudaGetSymbolAddress((void**)&v_ptr, g_v);

    dim3 grid(DD / 128, MT / 128);   // (8, 128)
    sgemm_bias_kernel<<<grid, 256>>>(x, Wq, bq, q_ptr);
    sgemm_bias_kernel<<<grid, 256>>>(x, Wk, bk, k_ptr);
    sgemm_bias_kernel<<<grid, 256>>>(x, Wv, bv, v_ptr);

    retention_scan_kernel<<<(BB * DD + 63) / 64, 64>>>(decay, out);
}

// round 4
// speedup vs baseline: 2.4660x; 2.4660x over previous
#include <cuda_runtime.h>
#include <cuda_bf16.h>
#include <cstdint>

#define BB 8
#define TT 2048
#define DD 1024
#define MT (BB * TT)   // 16384 rows

// ---------------- scratch (__device__ globals; no allocs allowed) -----------
__device__ float g_q[(size_t)MT * DD];
__device__ float g_k[(size_t)MT * DD];
__device__ float g_v[(size_t)MT * DD];           // holds kv after fused epilogue
__device__ __nv_bfloat16 g_xhi[(size_t)MT * DD];
__device__ __nv_bfloat16 g_xlo[(size_t)MT * DD];
__device__ __nv_bfloat16 g_whi[3][(size_t)DD * DD];
__device__ __nv_bfloat16 g_wlo[3][(size_t)DD * DD];
// scan intermediates
#define NCH 16
#define LCH 128
__device__ float g_finals[NCH * BB * DD];
__device__ float g_carries[NCH * BB * DD];

// ---------------- helpers ----------------------------------------------------
__device__ __forceinline__ uint32_t smem_to_u32(const void* p) {
    uint32_t a;
    asm("{ .reg .u64 t; cvta.to.shared.u64 t, %1; cvt.u32.u64 %0, t; }"
        : "=r"(a) : "l"(p));
    return a;
}
__device__ __forceinline__ void cp_async16(uint32_t saddr, const void* gptr) {
    asm volatile("cp.async.cg.shared.global [%0], [%1], 16;\n"
                 :: "r"(saddr), "l"(gptr));
}
__device__ __forceinline__ void cp_commit() {
    asm volatile("cp.async.commit_group;\n" ::: "memory");
}
__device__ __forceinline__ void cp_wait1() {
    asm volatile("cp.async.wait_group 1;\n" ::: "memory");
}
__device__ __forceinline__ void cp_wait0() {
    asm volatile("cp.async.wait_group 0;\n" ::: "memory");
}
__device__ __forceinline__ void ldm_x4(uint32_t* r, uint32_t addr) {
    asm volatile("ldmatrix.sync.aligned.m8n8.x4.shared.b16 {%0,%1,%2,%3}, [%4];"
                 : "=r"(r[0]), "=r"(r[1]), "=r"(r[2]), "=r"(r[3]) : "r"(addr));
}
__device__ __forceinline__ void ldm_x2(uint32_t* r, uint32_t addr) {
    asm volatile("ldmatrix.sync.aligned.m8n8.x2.shared.b16 {%0,%1}, [%2];"
                 : "=r"(r[0]), "=r"(r[1]) : "r"(addr));
}
__device__ __forceinline__ void mma_bf16(float* c, const uint32_t* a, const uint32_t* b) {
    asm volatile("mma.sync.aligned.m16n8k16.row.col.f32.bf16.bf16.f32 "
                 "{%0,%1,%2,%3}, {%4,%5,%6,%7}, {%8,%9}, {%0,%1,%2,%3};"
                 : "+f"(c[0]), "+f"(c[1]), "+f"(c[2]), "+f"(c[3])
                 : "r"(a[0]), "r"(a[1]), "r"(a[2]), "r"(a[3]),
                   "r"(b[0]), "r"(b[1]));
}

// ---------------- split fp32 -> bf16 hi/lo ----------------------------------
__global__ __launch_bounds__(256) void split_kernel(const float* __restrict__ src,
                                                    __nv_bfloat16* __restrict__ hi,
                                                    __nv_bfloat16* __restrict__ lo,
                                                    int n4) {
    int i = blockIdx.x * blockDim.x + threadIdx.x;
    if (i >= n4) return;
    float4 v = ((const float4*)src)[i];
    __nv_bfloat16 h[4], l[4];
    float f[4] = {v.x, v.y, v.z, v.w};
#pragma unroll
    for (int j = 0; j < 4; j++) {
        h[j] = __float2bfloat16_rn(f[j]);
        l[j] = __float2bfloat16_rn(f[j] - __bfloat162float(h[j]));
    }
    ((uint2*)hi)[i] = *(uint2*)h;
    ((uint2*)lo)[i] = *(uint2*)l;
}

// ---------------- HMMA bf16 split GEMM ---------------------------------------
// C[M,N] = (Ahi+Alo)[M,K] @ (Bhi+Blo)[N,K]^T (3 terms) + bias [, * mul]
// Block tile 128x128, BK=32, 8 warps (2m x 4n), warp tile 64x32.
// smem: 4 tiles (Ahi,Alo,Bhi,Blo) of 128 rows x 32 bf16, padded stride 40 elems.
#define ASTR 40                   // padded stride in bf16 elements (80 B)
#define TILE_SB (128 * ASTR * 2)  // 10240 bytes per tile
#define BUF_SB (4 * TILE_SB)      // 40960 bytes per buffer
#define NCHK (DD / 32)            // 32 chunks

__global__ __launch_bounds__(256, 1) void gemm_hmma_kernel(
    const __nv_bfloat16* __restrict__ Ahi, const __nv_bfloat16* __restrict__ Alo,
    const __nv_bfloat16* __restrict__ Bhi, const __nv_bfloat16* __restrict__ Blo,
    const float* __restrict__ bias, const float* __restrict__ mul,
    float* __restrict__ C) {
    extern __shared__ char smem[];
    const uint32_t smem_base = smem_to_u32(smem);
    const int tid = threadIdx.x;
    const int wid = tid >> 5;
    const int lane = tid & 31;
    const int warp_m = wid & 1;         // 2 warps in M
    const int warp_n = wid >> 1;        // 4 warps in N
    const int bm = blockIdx.y * 128;
    const int bn = blockIdx.x * 128;

    const __nv_bfloat16* srcs[4] = {Ahi, Alo, Bhi, Blo};
    const int rowbase[4] = {bm, bm, bn, bn};

    // ldmatrix per-lane address components
    const int lr = lane & 7;
    const int g = lane >> 3;                      // 0..3 (A .x4 groups)
    const uint32_t a_row = warp_m * 64 + (g & 1) * 8 + lr;
    const uint32_t a_koff = (g >> 1) * 8;
    const int bl = lane & 15;                     // B .x2 uses lanes 0..15
    const uint32_t b_row = warp_n * 32 + (bl & 7);
    const uint32_t b_koff = ((bl >> 3) & 1) * 8;

    float acc[4][4][4];
#pragma unroll
    for (int i = 0; i < 4; i++)
#pragma unroll
        for (int j = 0; j < 4; j++)
#pragma unroll
            for (int r = 0; r < 4; r++) acc[i][j][r] = 0.f;

    // ---- async tile loader: 4 tiles x 128 rows x 2 sixteen-B segs... (4 segs/row)
    auto issue_load = [&](int ch) {
        const int buf = ch & 1;
        const int k0 = ch * 32;
#pragma unroll
        for (int t = 0; t < 4; t++) {
            const __nv_bfloat16* src = srcs[t] + (size_t)rowbase[t] * DD + k0;
            const uint32_t sbase = smem_base + buf * BUF_SB + t * TILE_SB;
#pragma unroll
            for (int rep = 0; rep < 2; rep++) {
                const int idx = tid + rep * 256;      // 0..511
                const int r = idx >> 2, cseg = idx & 3;
                cp_async16(sbase + r * (ASTR * 2) + cseg * 16,
                           src + (size_t)r * DD + cseg * 8);
            }
        }
        cp_commit();
    };

    issue_load(0);

    for (int ch = 0; ch < NCHK; ch++) {
        if (ch + 1 < NCHK) {
            issue_load(ch + 1);
            cp_wait1();
        } else {
            cp_wait0();
        }
        __syncthreads();

        const uint32_t base = smem_base + (ch & 1) * BUF_SB;
#pragma unroll
        for (int ks = 0; ks < 2; ks++) {
            uint32_t ahi[4][4], alo[4][4], bhi[4][2], blo[4][2];
#pragma unroll
            for (int mt = 0; mt < 4; mt++) {
                uint32_t ar = base + (a_row + mt * 16) * (ASTR * 2)
                            + (ks * 16 + a_koff) * 2;
                ldm_x4(ahi[mt], ar);
                ldm_x4(alo[mt], ar + TILE_SB);
            }
#pragma unroll
            for (int nt = 0; nt < 4; nt++) {
                uint32_t br = base + 2 * TILE_SB + (b_row + nt * 8) * (ASTR * 2)
                            + (ks * 16 + b_koff) * 2;
                ldm_x2(bhi[nt], br);
                ldm_x2(blo[nt], br + TILE_SB);
            }
#pragma unroll
            for (int mt = 0; mt < 4; mt++)
#pragma unroll
                for (int nt = 0; nt < 4; nt++) {
                    mma_bf16(acc[mt][nt], ahi[mt], bhi[nt]);
                    mma_bf16(acc[mt][nt], ahi[mt], blo[nt]);
                    mma_bf16(acc[mt][nt], alo[mt], bhi[nt]);
                }
        }
        __syncthreads();   // before buffer (ch&1) is overwritten by load(ch+2)
    }

    // ---- epilogue: direct frag stores, bias (+ optional elementwise mul) ----
    const int qr = lane >> 2;           // 0..7
    const int qc = (lane & 3) * 2;      // 0,2,4,6
#pragma unroll
    for (int mt = 0; mt < 4; mt++) {
#pragma unroll
        for (int nt = 0; nt < 4; nt++) {
            const int row0 = bm + warp_m * 64 + mt * 16 + qr;
            const int col = bn + warp_n * 32 + nt * 8 + qc;
            const float2 bv = *(const float2*)&bias[col];
            float2 v0, v1;
            v0.x = acc[mt][nt][0] + bv.x;
            v0.y = acc[mt][nt][1] + bv.y;
            v1.x = acc[mt][nt][2] + bv.x;
            v1.y = acc[mt][nt][3] + bv.y;
            size_t o0 = (size_t)row0 * DD + col;
            size_t o1 = (size_t)(row0 + 8) * DD + col;
            if (mul != nullptr) {
                float2 m0 = *(const float2*)&mul[o0];
                float2 m1 = *(const float2*)&mul[o1];
                v0.x *= m0.x; v0.y *= m0.y;
                v1.x *= m1.x; v1.y *= m1.y;
            }
            *(float2*)&C[o0] = v0;
            *(float2*)&C[o1] = v1;
        }
    }
}

// ---------------- chunked scan ----------------------------------------------
// pass1: per (b,d,chunk) local scan of kv over LCH steps -> finals
__global__ __launch_bounds__(256) void scan1_kernel(const float* __restrict__ decay) {
    int x = blockIdx.x * blockDim.x + threadIdx.x;   // < NCH*BB*DD
    int d = x & (DD - 1);
    int b = (x >> 10) & (BB - 1);
    int c = x >> 13;
    float dec = decay[d];
    size_t base = (size_t)b * TT * DD + (size_t)c * LCH * DD + d;
    float mem = 0.f;
#pragma unroll 4
    for (int t = 0; t < LCH; t++)
        mem = fmaf(dec, mem, g_v[base + (size_t)t * DD]);
    g_finals[((size_t)c * BB + b) * DD + d] = mem;
}

// pass2: per (b,d) combine carries across chunks
__global__ __launch_bounds__(256) void scan2_kernel(const float* __restrict__ decay) {
    int x = blockIdx.x * blockDim.x + threadIdx.x;   // < BB*DD
    int d = x & (DD - 1);
    int b = x >> 10;
    float dec = decay[d];
    float pL = dec;
#pragma unroll
    for (int i = 0; i < 7; i++) pL *= pL;            // dec^128
    float carry = 0.f;
#pragma unroll
    for (int c = 0; c < NCH; c++) {
        size_t idx = ((size_t)c * BB + b) * DD + d;
        g_carries[idx] = carry;
        carry = fmaf(pL, carry, g_finals[idx]);
    }
}

// pass3: full scan with carry-in, emit out = q * mem
__global__ __launch_bounds__(256) void scan3_kernel(const float* __restrict__ decay,
                                                    float* __restrict__ out) {
    int x = blockIdx.x * blockDim.x + threadIdx.x;
    int d = x & (DD - 1);
    int b = (x >> 10) & (BB - 1);
    int c = x >> 13;
    float dec = decay[d];
    size_t base = (size_t)b * TT * DD + (size_t)c * LCH * DD + d;
    float mem = g_carries[((size_t)c * BB + b) * DD + d];
#pragma unroll 4
    for (int t = 0; t < LCH; t++) {
        size_t off = base + (size_t)t * DD;
        mem = fmaf(dec, mem, g_v[off]);
        out[off] = g_q[off] * mem;
    }
}

// ---------------- launch -----------------------------------------------------
extern "C" void kernel_launch(void* const* d_in, const int* in_sizes, int n_in,
                              void* d_out, int out_size) {
    const float* x     = (const float*)d_in[0];
    const float* Wq    = (const float*)d_in[1];
    const float* bq    = (const float*)d_in[2];
    const float* Wk    = (const float*)d_in[3];
    const float* bk    = (const float*)d_in[4];
    const float* Wv    = (const float*)d_in[5];
    const float* bv    = (const float*)d_in[6];
    const float* decay = (const float*)d_in[7];
    float* out = (float*)d_out;

    float *q_p, *k_p, *v_p;
    __nv_bfloat16 *xhi_p, *xlo_p, *whi_p, *wlo_p;
    cudaGetSymbolAddress((void**)&q_p, g_q);
    cudaGetSymbolAddress((void**)&k_p, g_k);
    cudaGetSymbolAddress((void**)&v_p, g_v);
    cudaGetSymbolAddress((void**)&xhi_p, g_xhi);
    cudaGetSymbolAddress((void**)&xlo_p, g_xlo);
    cudaGetSymbolAddress((void**)&whi_p, g_whi);
    cudaGetSymbolAddress((void**)&wlo_p, g_wlo);

    const size_t WN = (size_t)DD * DD;

    // hi/lo splits
    split_kernel<<<(MT * DD / 4) / 256, 256>>>(x, xhi_p, xlo_p, MT * DD / 4);
    split_kernel<<<(int)(WN / 4) / 256, 256>>>(Wq, whi_p + 0 * WN, wlo_p + 0 * WN, (int)(WN / 4));
    split_kernel<<<(int)(WN / 4) / 256, 256>>>(Wk, whi_p + 1 * WN, wlo_p + 1 * WN, (int)(WN / 4));
    split_kernel<<<(int)(WN / 4) / 256, 256>>>(Wv, whi_p + 2 * WN, wlo_p + 2 * WN, (int)(WN / 4));

    // HMMA GEMMs
    const int smem_bytes = 2 * BUF_SB;   // 81920
    cudaFuncSetAttribute(gemm_hmma_kernel, cudaFuncAttributeMaxDynamicSharedMemorySize, smem_bytes);
    dim3 grid(DD / 128, MT / 128);       // (8, 128)
    gemm_hmma_kernel<<<grid, 256, smem_bytes>>>(xhi_p, xlo_p, whi_p + 0 * WN, wlo_p + 0 * WN,
                                                bq, nullptr, q_p);
    gemm_hmma_kernel<<<grid, 256, smem_bytes>>>(xhi_p, xlo_p, whi_p + 1 * WN, wlo_p + 1 * WN,
                                                bk, nullptr, k_p);
    // V GEMM fuses kv = k * v into its epilogue (mul = k)
    gemm_hmma_kernel<<<grid, 256, smem_bytes>>>(xhi_p, xlo_p, whi_p + 2 * WN, wlo_p + 2 * WN,
                                                bv, k_p, v_p);

    // chunked scan
    scan1_kernel<<<(NCH * BB * DD) / 256, 256>>>(decay);
    scan2_kernel<<<(BB * DD) / 256, 256>>>(decay);
    scan3_kernel<<<(NCH * BB * DD) / 256, 256>>>(decay, out);
}

// round 5
// speedup vs baseline: 2.5052x; 1.0159x over previous
#include <cuda_runtime.h>
#include <cuda_bf16.h>
#include <cstdint>

#define BB 8
#define TT 2048
#define DD 1024
#define MT (BB * TT)   // 16384 rows

// ---------------- scratch (__device__ globals; no allocs allowed) -----------
__device__ float g_q[(size_t)MT * DD];
__device__ float g_k[(size_t)MT * DD];
__device__ float g_v[(size_t)MT * DD];           // holds kv after fused epilogue
__device__ __nv_bfloat16 g_xhi[(size_t)MT * DD];
__device__ __nv_bfloat16 g_xlo[(size_t)MT * DD];
__device__ __nv_bfloat16 g_whi[3][(size_t)DD * DD];
__device__ __nv_bfloat16 g_wlo[3][(size_t)DD * DD];
// scan intermediates
#define NCH 16
#define LCH 128
__device__ float g_finals[NCH * BB * DD];
__device__ float g_carries[NCH * BB * DD];

// ---------------- helpers ----------------------------------------------------
__device__ __forceinline__ uint32_t smem_to_u32(const void* p) {
    uint32_t a;
    asm("{ .reg .u64 t; cvta.to.shared.u64 t, %1; cvt.u32.u64 %0, t; }"
        : "=r"(a) : "l"(p));
    return a;
}
__device__ __forceinline__ void cp_async16(uint32_t saddr, const void* gptr) {
    asm volatile("cp.async.cg.shared.global [%0], [%1], 16;\n"
                 :: "r"(saddr), "l"(gptr));
}
__device__ __forceinline__ void cp_commit() {
    asm volatile("cp.async.commit_group;\n" ::: "memory");
}
__device__ __forceinline__ void cp_wait1() {
    asm volatile("cp.async.wait_group 1;\n" ::: "memory");
}
__device__ __forceinline__ void cp_wait0() {
    asm volatile("cp.async.wait_group 0;\n" ::: "memory");
}
__device__ __forceinline__ void ldm_x4(uint32_t* r, uint32_t addr) {
    asm volatile("ldmatrix.sync.aligned.m8n8.x4.shared.b16 {%0,%1,%2,%3}, [%4];"
                 : "=r"(r[0]), "=r"(r[1]), "=r"(r[2]), "=r"(r[3]) : "r"(addr));
}
__device__ __forceinline__ void mma_bf16(float* c, const uint32_t* a, const uint32_t* b) {
    asm volatile("mma.sync.aligned.m16n8k16.row.col.f32.bf16.bf16.f32 "
                 "{%0,%1,%2,%3}, {%4,%5,%6,%7}, {%8,%9}, {%0,%1,%2,%3};"
                 : "+f"(c[0]), "+f"(c[1]), "+f"(c[2]), "+f"(c[3])
                 : "r"(a[0]), "r"(a[1]), "r"(a[2]), "r"(a[3]),
                   "r"(b[0]), "r"(b[1]));
}

// ---------------- split fp32 -> bf16 hi/lo ----------------------------------
__global__ __launch_bounds__(256) void split_kernel(const float* __restrict__ src,
                                                    __nv_bfloat16* __restrict__ hi,
                                                    __nv_bfloat16* __restrict__ lo,
                                                    int n4) {
    int i = blockIdx.x * blockDim.x + threadIdx.x;
    if (i >= n4) return;
    float4 v = ((const float4*)src)[i];
    __nv_bfloat16 h[4], l[4];
    float f[4] = {v.x, v.y, v.z, v.w};
#pragma unroll
    for (int j = 0; j < 4; j++) {
        h[j] = __float2bfloat16_rn(f[j]);
        l[j] = __float2bfloat16_rn(f[j] - __bfloat162float(h[j]));
    }
    ((uint2*)hi)[i] = *(uint2*)h;
    ((uint2*)lo)[i] = *(uint2*)l;
}

// ---------------- HMMA bf16 split GEMM v2 ------------------------------------
// C[M,N] = (Ahi+Alo)[M,K] @ (Bhi+Blo)[N,K]^T (3 terms) + bias [, * mul]
// Block tile 128x256, BK=32, 8 warps (2m x 4n), warp tile 64x64.
// smem per stage: Ahi/Alo 128 rows + Bhi/Blo 256 rows, stride 40 bf16 (80B).
// 3-stage cp.async pipeline, one __syncthreads per chunk.
#define ASTR 40                    // padded row stride in bf16 elements
#define ROWB (ASTR * 2)            // 80 bytes
#define ST_A_HI 0
#define ST_A_LO (128 * ROWB)               // 10240
#define ST_B_HI (2 * 128 * ROWB)           // 20480
#define ST_B_LO (ST_B_HI + 256 * ROWB)     // 40960
#define STAGE_B (ST_B_LO + 256 * ROWB)     // 61440
#define NSTAGE 3
#define NCHK (DD / 32)             // 32 chunks

__global__ __launch_bounds__(256, 1) void gemm_hmma_kernel(
    const __nv_bfloat16* __restrict__ Ahi, const __nv_bfloat16* __restrict__ Alo,
    const __nv_bfloat16* __restrict__ Bhi, const __nv_bfloat16* __restrict__ Blo,
    const float* __restrict__ bias, const float* __restrict__ mul,
    float* __restrict__ C) {
    extern __shared__ char smem[];
    const uint32_t smem_base = smem_to_u32(smem);
    const int tid = threadIdx.x;
    const int wid = tid >> 5;
    const int lane = tid & 31;
    const int warp_m = wid & 1;          // 2 warps in M (64 rows each)
    const int warp_n = wid >> 1;         // 4 warps in N (64 cols each)
    const int bm = blockIdx.y * 128;
    const int bn = blockIdx.x * 256;

    // ldmatrix lane-address components
    const int lr = lane & 7;
    const int g = lane >> 3;                       // 0..3
    const uint32_t a_row = warp_m * 64 + (g & 1) * 8 + lr;   // + mt*16
    const uint32_t a_koff = (g >> 1) * 8;
    // B x4: groups -> (n0-7,k0),(n0-7,k8),(n8-15,k0),(n8-15,k8)
    const uint32_t b_row = warp_n * 64 + ((lane >> 4) << 3) + lr;  // + j*16
    const uint32_t b_koff = ((lane >> 3) & 1) * 8;

    float acc[4][8][4];
#pragma unroll
    for (int i = 0; i < 4; i++)
#pragma unroll
        for (int j = 0; j < 8; j++)
#pragma unroll
            for (int r = 0; r < 4; r++) acc[i][j][r] = 0.f;

    // ---- async tile loader -------------------------------------------------
    auto issue_load = [&](int ch) {
        const uint32_t sbase = smem_base + (ch % NSTAGE) * STAGE_B;
        const int k0 = ch * 32;
        // A tiles: 128 rows x 4 segs (16B) each, hi then lo
        {
            const __nv_bfloat16* sh = Ahi + (size_t)bm * DD + k0;
            const __nv_bfloat16* sl = Alo + (size_t)bm * DD + k0;
#pragma unroll
            for (int rep = 0; rep < 2; rep++) {
                const int idx = tid + rep * 256;        // 0..511
                const int r = idx >> 2, seg = idx & 3;
                cp_async16(sbase + ST_A_HI + r * ROWB + seg * 16,
                           sh + (size_t)r * DD + seg * 8);
                cp_async16(sbase + ST_A_LO + r * ROWB + seg * 16,
                           sl + (size_t)r * DD + seg * 8);
            }
        }
        // B tiles: 256 rows x 4 segs each, hi then lo
        {
            const __nv_bfloat16* sh = Bhi + (size_t)bn * DD + k0;
            const __nv_bfloat16* sl = Blo + (size_t)bn * DD + k0;
#pragma unroll
            for (int rep = 0; rep < 4; rep++) {
                const int idx = tid + rep * 256;        // 0..1023
                const int r = idx >> 2, seg = idx & 3;
                cp_async16(sbase + ST_B_HI + r * ROWB + seg * 16,
                           sh + (size_t)r * DD + seg * 8);
                cp_async16(sbase + ST_B_LO + r * ROWB + seg * 16,
                           sl + (size_t)r * DD + seg * 8);
            }
        }
        cp_commit();
    };

    issue_load(0);
    issue_load(1);

    for (int ch = 0; ch < NCHK; ch++) {
        if (ch == NCHK - 1) cp_wait0(); else cp_wait1();
        __syncthreads();
        if (ch + 2 < NCHK) issue_load(ch + 2);

        const uint32_t base = smem_base + (ch % NSTAGE) * STAGE_B;
#pragma unroll
        for (int ks = 0; ks < 2; ks++) {
            uint32_t ahi[4][4], alo[4][4], bhi[4][4], blo[4][4];
#pragma unroll
            for (int mt = 0; mt < 4; mt++) {
                uint32_t ar = base + (a_row + mt * 16) * ROWB
                            + (ks * 16 + a_koff) * 2;
                ldm_x4(ahi[mt], ar + ST_A_HI);
                ldm_x4(alo[mt], ar + ST_A_LO);
            }
#pragma unroll
            for (int j = 0; j < 4; j++) {             // each covers 2 n-tiles
                uint32_t br = base + (b_row + j * 16) * ROWB
                            + (ks * 16 + b_koff) * 2;
                ldm_x4(bhi[j], br + ST_B_HI);
                ldm_x4(blo[j], br + ST_B_LO);
            }
#pragma unroll
            for (int mt = 0; mt < 4; mt++)
#pragma unroll
                for (int nt = 0; nt < 8; nt++) {
                    const uint32_t* bh = &bhi[nt >> 1][(nt & 1) * 2];
                    const uint32_t* bl = &blo[nt >> 1][(nt & 1) * 2];
                    mma_bf16(acc[mt][nt], ahi[mt], bh);
                    mma_bf16(acc[mt][nt], ahi[mt], bl);
                    mma_bf16(acc[mt][nt], alo[mt], bh);
                }
        }
    }

    // ---- epilogue: direct frag stores, bias (+ optional elementwise mul) ----
    const int qr = lane >> 2;           // 0..7
    const int qc = (lane & 3) * 2;      // 0,2,4,6
#pragma unroll
    for (int mt = 0; mt < 4; mt++) {
#pragma unroll
        for (int nt = 0; nt < 8; nt++) {
            const int row0 = bm + warp_m * 64 + mt * 16 + qr;
            const int col = bn + warp_n * 64 + nt * 8 + qc;
            const float2 bv = *(const float2*)&bias[col];
            float2 v0, v1;
            v0.x = acc[mt][nt][0] + bv.x;
            v0.y = acc[mt][nt][1] + bv.y;
            v1.x = acc[mt][nt][2] + bv.x;
            v1.y = acc[mt][nt][3] + bv.y;
            size_t o0 = (size_t)row0 * DD + col;
            size_t o1 = (size_t)(row0 + 8) * DD + col;
            if (mul != nullptr) {
                float2 m0 = *(const float2*)&mul[o0];
                float2 m1 = *(const float2*)&mul[o1];
                v0.x *= m0.x; v0.y *= m0.y;
                v1.x *= m1.x; v1.y *= m1.y;
            }
            *(float2*)&C[o0] = v0;
            *(float2*)&C[o1] = v1;
        }
    }
}

// ---------------- chunked scan ----------------------------------------------
__global__ __launch_bounds__(256) void scan1_kernel(const float* __restrict__ decay) {
    int x = blockIdx.x * blockDim.x + threadIdx.x;   // < NCH*BB*DD
    int d = x & (DD - 1);
    int b = (x >> 10) & (BB - 1);
    int c = x >> 13;
    float dec = decay[d];
    size_t base = (size_t)b * TT * DD + (size_t)c * LCH * DD + d;
    float mem = 0.f;
#pragma unroll 4
    for (int t = 0; t < LCH; t++)
        mem = fmaf(dec, mem, g_v[base + (size_t)t * DD]);
    g_finals[((size_t)c * BB + b) * DD + d] = mem;
}

__global__ __launch_bounds__(256) void scan2_kernel(const float* __restrict__ decay) {
    int x = blockIdx.x * blockDim.x + threadIdx.x;   // < BB*DD
    int d = x & (DD - 1);
    int b = x >> 10;
    float dec = decay[d];
    float pL = dec;
#pragma unroll
    for (int i = 0; i < 7; i++) pL *= pL;            // dec^128
    float carry = 0.f;
#pragma unroll
    for (int c = 0; c < NCH; c++) {
        size_t idx = ((size_t)c * BB + b) * DD + d;
        g_carries[idx] = carry;
        carry = fmaf(pL, carry, g_finals[idx]);
    }
}

__global__ __launch_bounds__(256) void scan3_kernel(const float* __restrict__ decay,
                                                    float* __restrict__ out) {
    int x = blockIdx.x * blockDim.x + threadIdx.x;
    int d = x & (DD - 1);
    int b = (x >> 10) & (BB - 1);
    int c = x >> 13;
    float dec = decay[d];
    size_t base = (size_t)b * TT * DD + (size_t)c * LCH * DD + d;
    float mem = g_carries[((size_t)c * BB + b) * DD + d];
#pragma unroll 4
    for (int t = 0; t < LCH; t++) {
        size_t off = base + (size_t)t * DD;
        mem = fmaf(dec, mem, g_v[off]);
        out[off] = g_q[off] * mem;
    }
}

// ---------------- launch -----------------------------------------------------
extern "C" void kernel_launch(void* const* d_in, const int* in_sizes, int n_in,
                              void* d_out, int out_size) {
    const float* x     = (const float*)d_in[0];
    const float* Wq    = (const float*)d_in[1];
    const float* bq    = (const float*)d_in[2];
    const float* Wk    = (const float*)d_in[3];
    const float* bk    = (const float*)d_in[4];
    const float* Wv    = (const float*)d_in[5];
    const float* bv    = (const float*)d_in[6];
    const float* decay = (const float*)d_in[7];
    float* out = (float*)d_out;

    float *q_p, *k_p, *v_p;
    __nv_bfloat16 *xhi_p, *xlo_p, *whi_p, *wlo_p;
    cudaGetSymbolAddress((void**)&q_p, g_q);
    cudaGetSymbolAddress((void**)&k_p, g_k);
    cudaGetSymbolAddress((void**)&v_p, g_v);
    cudaGetSymbolAddress((void**)&xhi_p, g_xhi);
    cudaGetSymbolAddress((void**)&xlo_p, g_xlo);
    cudaGetSymbolAddress((void**)&whi_p, g_whi);
    cudaGetSymbolAddress((void**)&wlo_p, g_wlo);

    const size_t WN = (size_t)DD * DD;

    // hi/lo splits
    split_kernel<<<(MT * DD / 4) / 256, 256>>>(x, xhi_p, xlo_p, MT * DD / 4);
    split_kernel<<<(int)(WN / 4) / 256, 256>>>(Wq, whi_p + 0 * WN, wlo_p + 0 * WN, (int)(WN / 4));
    split_kernel<<<(int)(WN / 4) / 256, 256>>>(Wk, whi_p + 1 * WN, wlo_p + 1 * WN, (int)(WN / 4));
    split_kernel<<<(int)(WN / 4) / 256, 256>>>(Wv, whi_p + 2 * WN, wlo_p + 2 * WN, (int)(WN / 4));

    // HMMA GEMMs
    const int smem_bytes = NSTAGE * STAGE_B;   // 184320
    cudaFuncSetAttribute(gemm_hmma_kernel, cudaFuncAttributeMaxDynamicSharedMemorySize, smem_bytes);
    dim3 grid(DD / 256, MT / 128);             // (4, 128)
    gemm_hmma_kernel<<<grid, 256, smem_bytes>>>(xhi_p, xlo_p, whi_p + 0 * WN, wlo_p + 0 * WN,
                                                bq, nullptr, q_p);
    gemm_hmma_kernel<<<grid, 256, smem_bytes>>>(xhi_p, xlo_p, whi_p + 1 * WN, wlo_p + 1 * WN,
                                                bk, nullptr, k_p);
    // V GEMM fuses kv = k * v into its epilogue (mul = k)
    gemm_hmma_kernel<<<grid, 256, smem_bytes>>>(xhi_p, xlo_p, whi_p + 2 * WN, wlo_p + 2 * WN,
                                                bv, k_p, v_p);

    // chunked scan
    scan1_kernel<<<(NCH * BB * DD) / 256, 256>>>(decay);
    scan2_kernel<<<(BB * DD) / 256, 256>>>(decay);
    scan3_kernel<<<(NCH * BB * DD) / 256, 256>>>(decay, out);
}

// round 6
// speedup vs baseline: 2.7066x; 1.0804x over previous
#include <cuda_runtime.h>
#include <cuda_bf16.h>
#include <cstdint>

#define BB 8
#define TT 2048
#define DD 1024
#define MT (BB * TT)   // 16384 rows

// ---------------- scratch (__device__ globals; no allocs allowed) -----------
__device__ float g_q[(size_t)MT * DD];
__device__ float g_k[(size_t)MT * DD];
__device__ float g_v[(size_t)MT * DD];
__device__ __nv_bfloat16 g_xhi[(size_t)MT * DD];
__device__ __nv_bfloat16 g_xlo[(size_t)MT * DD];
__device__ __nv_bfloat16 g_whi[3][(size_t)DD * DD];   // stacked: q,k,v -> rows 0..3071
__device__ __nv_bfloat16 g_wlo[3][(size_t)DD * DD];
// scan intermediates
#define NCH 16
#define LCH 128
__device__ float g_finals[NCH * BB * DD];
__device__ float g_carries[NCH * BB * DD];

// ---------------- helpers ----------------------------------------------------
__device__ __forceinline__ uint32_t smem_to_u32(const void* p) {
    uint32_t a;
    asm("{ .reg .u64 t; cvta.to.shared.u64 t, %1; cvt.u32.u64 %0, t; }"
        : "=r"(a) : "l"(p));
    return a;
}
__device__ __forceinline__ void cp_async16(uint32_t saddr, const void* gptr) {
    asm volatile("cp.async.cg.shared.global [%0], [%1], 16;\n"
                 :: "r"(saddr), "l"(gptr));
}
__device__ __forceinline__ void cp_commit() {
    asm volatile("cp.async.commit_group;\n" ::: "memory");
}
__device__ __forceinline__ void cp_wait1() {
    asm volatile("cp.async.wait_group 1;\n" ::: "memory");
}
__device__ __forceinline__ void cp_wait0() {
    asm volatile("cp.async.wait_group 0;\n" ::: "memory");
}
__device__ __forceinline__ void ldm_x4(uint32_t* r, uint32_t addr) {
    asm volatile("ldmatrix.sync.aligned.m8n8.x4.shared.b16 {%0,%1,%2,%3}, [%4];"
                 : "=r"(r[0]), "=r"(r[1]), "=r"(r[2]), "=r"(r[3]) : "r"(addr));
}
__device__ __forceinline__ void mma_bf16(float* c, const uint32_t* a, const uint32_t* b) {
    asm volatile("mma.sync.aligned.m16n8k16.row.col.f32.bf16.bf16.f32 "
                 "{%0,%1,%2,%3}, {%4,%5,%6,%7}, {%8,%9}, {%0,%1,%2,%3};"
                 : "+f"(c[0]), "+f"(c[1]), "+f"(c[2]), "+f"(c[3])
                 : "r"(a[0]), "r"(a[1]), "r"(a[2]), "r"(a[3]),
                   "r"(b[0]), "r"(b[1]));
}

// ---------------- split fp32 -> bf16 hi/lo ----------------------------------
__global__ __launch_bounds__(256) void split_kernel(const float* __restrict__ src,
                                                    __nv_bfloat16* __restrict__ hi,
                                                    __nv_bfloat16* __restrict__ lo,
                                                    int n4) {
    int i = blockIdx.x * blockDim.x + threadIdx.x;
    if (i >= n4) return;
    float4 v = ((const float4*)src)[i];
    __nv_bfloat16 h[4], l[4];
    float f[4] = {v.x, v.y, v.z, v.w};
#pragma unroll
    for (int j = 0; j < 4; j++) {
        h[j] = __float2bfloat16_rn(f[j]);
        l[j] = __float2bfloat16_rn(f[j] - __bfloat162float(h[j]));
    }
    ((uint2*)hi)[i] = *(uint2*)h;
    ((uint2*)lo)[i] = *(uint2*)l;
}

// ---------------- fused QKV HMMA bf16 split GEMM -----------------------------
// C_seg[M,1024] = (Ahi+Alo)[M,K] @ (Whi+Wlo)[3072,K]^T (3 terms) + bias_seg
// Block tile 128x256, BK=32, 8 warps (2m x 4n), warp tile 64x64.
// One launch over N=3072; segment (q/k/v) chosen from bn>>10.
#define ASTR 40                    // padded row stride in bf16 elements
#define ROWB (ASTR * 2)            // 80 bytes
#define ST_A_HI 0
#define ST_A_LO (128 * ROWB)               // 10240
#define ST_B_HI (2 * 128 * ROWB)           // 20480
#define ST_B_LO (ST_B_HI + 256 * ROWB)     // 40960
#define STAGE_B (ST_B_LO + 256 * ROWB)     // 61440
#define NSTAGE 3
#define NCHK (DD / 32)             // 32 chunks

__global__ __launch_bounds__(256, 1) void gemm_qkv_kernel(
    const __nv_bfloat16* __restrict__ Ahi, const __nv_bfloat16* __restrict__ Alo,
    const __nv_bfloat16* __restrict__ Whi, const __nv_bfloat16* __restrict__ Wlo,
    const float* __restrict__ bq, const float* __restrict__ bk,
    const float* __restrict__ bv,
    float* __restrict__ Cq, float* __restrict__ Ck, float* __restrict__ Cv) {
    extern __shared__ char smem[];
    const uint32_t smem_base = smem_to_u32(smem);
    const int tid = threadIdx.x;
    const int wid = tid >> 5;
    const int lane = tid & 31;
    const int warp_m = wid & 1;          // 2 warps in M (64 rows each)
    const int warp_n = wid >> 1;         // 4 warps in N (64 cols each)
    const int bm = blockIdx.y * 128;
    const int bn = blockIdx.x * 256;     // 0..3071 within stacked W
    const int seg = bn >> 10;            // 0=q, 1=k, 2=v
    const int cn = bn & (DD - 1);        // column base within segment

    const float* bias = (seg == 0) ? bq : (seg == 1) ? bk : bv;
    float* C = (seg == 0) ? Cq : (seg == 1) ? Ck : Cv;

    // ldmatrix lane-address components
    const int lr = lane & 7;
    const int g = lane >> 3;                       // 0..3
    const uint32_t a_row = warp_m * 64 + (g & 1) * 8 + lr;   // + mt*16
    const uint32_t a_koff = (g >> 1) * 8;
    const uint32_t b_row = warp_n * 64 + ((lane >> 4) << 3) + lr;  // + j*16
    const uint32_t b_koff = ((lane >> 3) & 1) * 8;

    float acc[4][8][4];
#pragma unroll
    for (int i = 0; i < 4; i++)
#pragma unroll
        for (int j = 0; j < 8; j++)
#pragma unroll
            for (int r = 0; r < 4; r++) acc[i][j][r] = 0.f;

    // ---- async tile loader -------------------------------------------------
    auto issue_load = [&](int ch) {
        const uint32_t sbase = smem_base + (ch % NSTAGE) * STAGE_B;
        const int k0 = ch * 32;
        {
            const __nv_bfloat16* sh = Ahi + (size_t)bm * DD + k0;
            const __nv_bfloat16* sl = Alo + (size_t)bm * DD + k0;
#pragma unroll
            for (int rep = 0; rep < 2; rep++) {
                const int idx = tid + rep * 256;        // 0..511
                const int r = idx >> 2, segi = idx & 3;
                cp_async16(sbase + ST_A_HI + r * ROWB + segi * 16,
                           sh + (size_t)r * DD + segi * 8);
                cp_async16(sbase + ST_A_LO + r * ROWB + segi * 16,
                           sl + (size_t)r * DD + segi * 8);
            }
        }
        {
            const __nv_bfloat16* sh = Whi + (size_t)bn * DD + k0;
            const __nv_bfloat16* sl = Wlo + (size_t)bn * DD + k0;
#pragma unroll
            for (int rep = 0; rep < 4; rep++) {
                const int idx = tid + rep * 256;        // 0..1023
                const int r = idx >> 2, segi = idx & 3;
                cp_async16(sbase + ST_B_HI + r * ROWB + segi * 16,
                           sh + (size_t)r * DD + segi * 8);
                cp_async16(sbase + ST_B_LO + r * ROWB + segi * 16,
                           sl + (size_t)r * DD + segi * 8);
            }
        }
        cp_commit();
    };

    issue_load(0);
    issue_load(1);

    for (int ch = 0; ch < NCHK; ch++) {
        if (ch == NCHK - 1) cp_wait0(); else cp_wait1();
        __syncthreads();
        if (ch + 2 < NCHK) issue_load(ch + 2);

        const uint32_t base = smem_base + (ch % NSTAGE) * STAGE_B;
#pragma unroll
        for (int ks = 0; ks < 2; ks++) {
            uint32_t ahi[4][4], alo[4][4], bhi[4][4], blo[4][4];
#pragma unroll
            for (int mt = 0; mt < 4; mt++) {
                uint32_t ar = base + (a_row + mt * 16) * ROWB
                            + (ks * 16 + a_koff) * 2;
                ldm_x4(ahi[mt], ar + ST_A_HI);
                ldm_x4(alo[mt], ar + ST_A_LO);
            }
#pragma unroll
            for (int j = 0; j < 4; j++) {             // each covers 2 n-tiles
                uint32_t br = base + (b_row + j * 16) * ROWB
                            + (ks * 16 + b_koff) * 2;
                ldm_x4(bhi[j], br + ST_B_HI);
                ldm_x4(blo[j], br + ST_B_LO);
            }
#pragma unroll
            for (int mt = 0; mt < 4; mt++)
#pragma unroll
                for (int nt = 0; nt < 8; nt++) {
                    const uint32_t* bh = &bhi[nt >> 1][(nt & 1) * 2];
                    const uint32_t* bl = &blo[nt >> 1][(nt & 1) * 2];
                    mma_bf16(acc[mt][nt], ahi[mt], bh);
                    mma_bf16(acc[mt][nt], ahi[mt], bl);
                    mma_bf16(acc[mt][nt], alo[mt], bh);
                }
        }
    }

    // ---- epilogue: direct frag stores + bias --------------------------------
    const int qr = lane >> 2;           // 0..7
    const int qc = (lane & 3) * 2;      // 0,2,4,6
#pragma unroll
    for (int mt = 0; mt < 4; mt++) {
#pragma unroll
        for (int nt = 0; nt < 8; nt++) {
            const int row0 = bm + warp_m * 64 + mt * 16 + qr;
            const int col = cn + warp_n * 64 + nt * 8 + qc;
            const float2 bvv = *(const float2*)&bias[col];
            float2 v0, v1;
            v0.x = acc[mt][nt][0] + bvv.x;
            v0.y = acc[mt][nt][1] + bvv.y;
            v1.x = acc[mt][nt][2] + bvv.x;
            v1.y = acc[mt][nt][3] + bvv.y;
            *(float2*)&C[(size_t)row0 * DD + col] = v0;
            *(float2*)&C[(size_t)(row0 + 8) * DD + col] = v1;
        }
    }
}

// ---------------- chunked scan (kv = k*v computed inline) --------------------
__global__ __launch_bounds__(256) void scan1_kernel(const float* __restrict__ decay) {
    int x = blockIdx.x * blockDim.x + threadIdx.x;   // < NCH*BB*DD
    int d = x & (DD - 1);
    int b = (x >> 10) & (BB - 1);
    int c = x >> 13;
    float dec = decay[d];
    size_t base = (size_t)b * TT * DD + (size_t)c * LCH * DD + d;
    float mem = 0.f;
#pragma unroll 4
    for (int t = 0; t < LCH; t++) {
        size_t off = base + (size_t)t * DD;
        mem = fmaf(dec, mem, g_k[off] * g_v[off]);
    }
    g_finals[((size_t)c * BB + b) * DD + d] = mem;
}

__global__ __launch_bounds__(256) void scan2_kernel(const float* __restrict__ decay) {
    int x = blockIdx.x * blockDim.x + threadIdx.x;   // < BB*DD
    int d = x & (DD - 1);
    int b = x >> 10;
    float dec = decay[d];
    float pL = dec;
#pragma unroll
    for (int i = 0; i < 7; i++) pL *= pL;            // dec^128
    float carry = 0.f;
#pragma unroll
    for (int c = 0; c < NCH; c++) {
        size_t idx = ((size_t)c * BB + b) * DD + d;
        g_carries[idx] = carry;
        carry = fmaf(pL, carry, g_finals[idx]);
    }
}

__global__ __launch_bounds__(256) void scan3_kernel(const float* __restrict__ decay,
                                                    float* __restrict__ out) {
    int x = blockIdx.x * blockDim.x + threadIdx.x;
    int d = x & (DD - 1);
    int b = (x >> 10) & (BB - 1);
    int c = x >> 13;
    float dec = decay[d];
    size_t base = (size_t)b * TT * DD + (size_t)c * LCH * DD + d;
    float mem = g_carries[((size_t)c * BB + b) * DD + d];
#pragma unroll 4
    for (int t = 0; t < LCH; t++) {
        size_t off = base + (size_t)t * DD;
        mem = fmaf(dec, mem, g_k[off] * g_v[off]);
        out[off] = g_q[off] * mem;
    }
}

// ---------------- launch -----------------------------------------------------
extern "C" void kernel_launch(void* const* d_in, const int* in_sizes, int n_in,
                              void* d_out, int out_size) {
    const float* x     = (const float*)d_in[0];
    const float* Wq    = (const float*)d_in[1];
    const float* bq    = (const float*)d_in[2];
    const float* Wk    = (const float*)d_in[3];
    const float* bk    = (const float*)d_in[4];
    const float* Wv    = (const float*)d_in[5];
    const float* bv    = (const float*)d_in[6];
    const float* decay = (const float*)d_in[7];
    float* out = (float*)d_out;

    float *q_p, *k_p, *v_p;
    __nv_bfloat16 *xhi_p, *xlo_p, *whi_p, *wlo_p;
    cudaGetSymbolAddress((void**)&q_p, g_q);
    cudaGetSymbolAddress((void**)&k_p, g_k);
    cudaGetSymbolAddress((void**)&v_p, g_v);
    cudaGetSymbolAddress((void**)&xhi_p, g_xhi);
    cudaGetSymbolAddress((void**)&xlo_p, g_xlo);
    cudaGetSymbolAddress((void**)&whi_p, g_whi);
    cudaGetSymbolAddress((void**)&wlo_p, g_wlo);

    const size_t WN = (size_t)DD * DD;

    // hi/lo splits
    split_kernel<<<(MT * DD / 4) / 256, 256>>>(x, xhi_p, xlo_p, MT * DD / 4);
    split_kernel<<<(int)(WN / 4) / 256, 256>>>(Wq, whi_p + 0 * WN, wlo_p + 0 * WN, (int)(WN / 4));
    split_kernel<<<(int)(WN / 4) / 256, 256>>>(Wk, whi_p + 1 * WN, wlo_p + 1 * WN, (int)(WN / 4));
    split_kernel<<<(int)(WN / 4) / 256, 256>>>(Wv, whi_p + 2 * WN, wlo_p + 2 * WN, (int)(WN / 4));

    // fused QKV HMMA GEMM (single launch, N=3072)
    const int smem_bytes = NSTAGE * STAGE_B;   // 184320
    cudaFuncSetAttribute(gemm_qkv_kernel, cudaFuncAttributeMaxDynamicSharedMemorySize, smem_bytes);
    dim3 grid(3 * DD / 256, MT / 128);         // (12, 128) = 1536 CTAs
    gemm_qkv_kernel<<<grid, 256, smem_bytes>>>(xhi_p, xlo_p, whi_p, wlo_p,
                                               bq, bk, bv, q_p, k_p, v_p);

    // chunked scan
    scan1_kernel<<<(NCH * BB * DD) / 256, 256>>>(decay);
    scan2_kernel<<<(BB * DD) / 256, 256>>>(decay);
    scan3_kernel<<<(NCH * BB * DD) / 256, 256>>>(decay, out);
}